// round 15
// baseline (speedup 1.0000x reference)
#include <cuda_runtime.h>

// Bundle-adjustment reprojection residual — fused single persistent kernel.
//   d_in[0] observes  float32 [N_OBS, 2]
//   d_in[1] K         float32 [3, 3]
//   d_in[2] poses     float32 [N_CAM, 7]   (t[3], qv[3], qw)
//   d_in[3] points    float32 [N_PTS, 3]
//   d_in[4] cidx      int32   [N_OBS]
//   d_in[5] pidx      int32   [N_OBS]
// Output: float32 [N_OBS*2]  residual = proj - observe
//
// R15:
//  - fused: pose->smem staging + point repack + ticket grid barrier + main loop
//  - 448 threads x 2/SM (reg cap 73): batch-4 main loop with INDEX-ONLY
//    prefetch — next iteration's cidx4/pidx4/obs4 loaded during current
//    compute, so point LDG.128s issue immediately at loop top.

#define THREADS 448
#define N_PTS_MAX 500032

__device__ float4 g_points4[N_PTS_MAX];
__device__ unsigned int g_ticket;   // monotonically increasing; never reset

__global__ __launch_bounds__(THREADS, 2) void residual_fused_kernel(
    const float4* __restrict__ obs4,
    const float* __restrict__ K,
    const float* __restrict__ poses,
    const float4* __restrict__ points4,
    const float* __restrict__ points,
    const int4* __restrict__ cidx4,
    const int4* __restrict__ pidx4,
    float4* __restrict__ out4,
    int n_obs, int n_cam, int n_pts)
{
    extern __shared__ float4 psm[];   // [n_cam] a-rows then [n_cam] b-rows
    float4* pa_t = psm;               // tx ty tz qx
    float4* pb_t = psm + n_cam;       // qy qz qw pad

    const int tid = threadIdx.x;
    const int nblocks = gridDim.x;
    const int g = blockIdx.x * THREADS + tid;
    const int gsz = nblocks * THREADS;

    // ---------------- phase 1a: stage poses into smem ----------------
    {
        float* a_f = (float*)pa_t;
        float* b_f = (float*)pb_t;
        const int n_pose_f = n_cam * 7;
        for (int idx = tid; idx < n_pose_f; idx += THREADS) {
            int c = idx / 7;
            int k = idx - c * 7;
            float v = __ldg(&poses[idx]);
            if (k < 4) a_f[c * 4 + k] = v;
            else       b_f[c * 4 + (k - 4)] = v;
        }
    }

    // ---------------- phase 1b: repack points slice ----------------
    {
        const int pq = n_pts >> 2;  // groups of 4 points (12 floats = 3 float4)
        for (int i = g; i < pq; i += gsz) {
            float4 v0 = __ldg(&points4[3 * i]);
            float4 v1 = __ldg(&points4[3 * i + 1]);
            float4 v2 = __ldg(&points4[3 * i + 2]);
            g_points4[4 * i + 0] = make_float4(v0.x, v0.y, v0.z, 0.0f);
            g_points4[4 * i + 1] = make_float4(v0.w, v1.x, v1.y, 0.0f);
            g_points4[4 * i + 2] = make_float4(v1.z, v1.w, v2.x, 0.0f);
            g_points4[4 * i + 3] = make_float4(v2.y, v2.z, v2.w, 0.0f);
        }
        int r = (pq << 2) + g;
        if (r < n_pts) {
            const float* p = points + (size_t)r * 3;
            g_points4[r] = make_float4(__ldg(p), __ldg(p + 1), __ldg(p + 2), 0.0f);
        }
    }

    // ------------- ticket grid barrier (no reset across launches) -------------
    __threadfence();
    __syncthreads();
    if (tid == 0) {
        unsigned t = atomicAdd(&g_ticket, 1u);
        unsigned target = (t / (unsigned)nblocks + 1u) * (unsigned)nblocks;
        unsigned v;
        do {
            asm volatile("ld.global.acquire.gpu.u32 %0, [%1];"
                         : "=r"(v) : "l"(&g_ticket));
            if (v >= target) break;
            __nanosleep(64);
        } while (true);
    }
    __syncthreads();

    // ---------------- phase 2: main loop, 4 obs/thread, idx prefetch ----------
    const float fx = __ldg(&K[0]);
    const float cxx = __ldg(&K[2]);
    const float fy = __ldg(&K[4]);
    const float cyy = __ldg(&K[5]);

    const int n_quads = n_obs >> 2;

    int q = g;
    int4 c4, p4;
    float4 ob0, ob1;
    if (q < n_quads) {
        c4  = __ldg(&cidx4[q]);
        p4  = __ldg(&pidx4[q]);
        ob0 = __ldg(&obs4[2 * q]);
        ob1 = __ldg(&obs4[2 * q + 1]);
    }

    while (q < n_quads) {
        // points for THIS iteration fire immediately (indices already resident)
        float4 pt0 = __ldg(&g_points4[p4.x]);
        float4 pt1 = __ldg(&g_points4[p4.y]);
        float4 pt2 = __ldg(&g_points4[p4.z]);
        float4 pt3 = __ldg(&g_points4[p4.w]);

        // prefetch NEXT iteration's indices + observes (independent streams)
        const int qn = q + gsz;
        const int qs = (qn < n_quads) ? qn : q;
        int4 c4n   = __ldg(&cidx4[qs]);
        int4 p4n   = __ldg(&pidx4[qs]);
        float4 nb0 = __ldg(&obs4[2 * qs]);
        float4 nb1 = __ldg(&obs4[2 * qs + 1]);

        int cis[4] = {c4.x, c4.y, c4.z, c4.w};

        // pose gathers from smem (latency covered while point LDGs fly)
        float4 pa[4], pb[4];
        #pragma unroll
        for (int j = 0; j < 4; j++) {
            pa[j] = pa_t[cis[j]];
            pb[j] = pb_t[cis[j]];
        }

        float4 ptc[4] = {pt0, pt1, pt2, pt3};
        float obx[4] = {ob0.x, ob0.z, ob1.x, ob1.z};
        float oby[4] = {ob0.y, ob0.w, ob1.y, ob1.w};
        float res[8];

        #pragma unroll
        for (int j = 0; j < 4; j++) {
            float tx = pa[j].x, ty = pa[j].y, tz = pa[j].z;
            float qx = pa[j].w, qy = pb[j].x, qz = pb[j].y, qw = pb[j].z;
            float X = ptc[j].x, Y = ptc[j].y, Z = ptc[j].z;

            float uvx = qy * Z - qz * Y;
            float uvy = qz * X - qx * Z;
            float uvz = qx * Y - qy * X;
            float wx = fmaf(qw, X, uvx);
            float wy = fmaf(qw, Y, uvy);
            float wz = fmaf(qw, Z, uvz);
            float c2x = qy * wz - qz * wy;
            float c2y = qz * wx - qx * wz;
            float c2z = qx * wy - qy * wx;
            float Xc = fmaf(2.0f, c2x, X) + tx;
            float Yc = fmaf(2.0f, c2y, Y) + ty;
            float Zc = fmaf(2.0f, c2z, Z) + tz;

            float invz = __fdividef(1.0f, Zc);
            res[2 * j + 0] = fmaf(fx * Xc, invz, cxx) - obx[j];
            res[2 * j + 1] = fmaf(fy * Yc, invz, cyy) - oby[j];
        }

        out4[2 * q]     = make_float4(res[0], res[1], res[2], res[3]);
        out4[2 * q + 1] = make_float4(res[4], res[5], res[6], res[7]);

        // rotate prefetched state
        c4 = c4n; p4 = p4n; ob0 = nb0; ob1 = nb1;
        q = qn;
    }

    // ---- tail: n_obs % 4 leftovers (block 0; empty for N_OBS=5M) ----
    const int rem_base = n_quads << 2;
    if (blockIdx.x == 0) {
        const int* cidx = (const int*)cidx4;
        const int* pidx = (const int*)pidx4;
        const float2* obs2 = (const float2*)obs4;
        float2* out2 = (float2*)out4;
        for (int i = rem_base + tid; i < n_obs; i += THREADS) {
            int ci = __ldg(&cidx[i]);
            int pi = __ldg(&pidx[i]);
            float4 a = pa_t[ci];
            float4 b = pb_t[ci];
            float tx = a.x, ty = a.y, tz = a.z;
            float qx = a.w, qy = b.x, qz = b.y, qw = b.z;
            float4 p = __ldg(&g_points4[pi]);
            float X = p.x, Y = p.y, Z = p.z;

            float uvx = qy * Z - qz * Y;
            float uvy = qz * X - qx * Z;
            float uvz = qx * Y - qy * X;
            float wx = fmaf(qw, X, uvx);
            float wy = fmaf(qw, Y, uvy);
            float wz = fmaf(qw, Z, uvz);
            float c2x = qy * wz - qz * wy;
            float c2y = qz * wx - qx * wz;
            float c2z = qx * wy - qy * wx;
            float Xc = fmaf(2.0f, c2x, X) + tx;
            float Yc = fmaf(2.0f, c2y, Y) + ty;
            float Zc = fmaf(2.0f, c2z, Z) + tz;
            float invz = __fdividef(1.0f, Zc);
            float2 ob = __ldg(&obs2[i]);
            float2 r;
            r.x = fmaf(fx * Xc, invz, cxx) - ob.x;
            r.y = fmaf(fy * Yc, invz, cyy) - ob.y;
            out2[i] = r;
        }
    }
}

extern "C" void kernel_launch(void* const* d_in, const int* in_sizes, int n_in,
                              void* d_out, int out_size) {
    const float* observes = (const float*)d_in[0];
    const float* K        = (const float*)d_in[1];
    const float* poses    = (const float*)d_in[2];
    const float* points   = (const float*)d_in[3];
    const int* cidx       = (const int*)d_in[4];
    const int* pidx       = (const int*)d_in[5];

    int n_obs = in_sizes[0] / 2;
    int n_cam = in_sizes[2] / 7;
    int n_pts = in_sizes[3] / 3;
    if (n_pts > N_PTS_MAX) n_pts = N_PTS_MAX;

    int smem = n_cam * 2 * sizeof(float4);  // 64000 B for n_cam=2000

    cudaFuncSetAttribute(residual_fused_kernel,
                         cudaFuncAttributeMaxDynamicSharedMemorySize, smem);

    int num_sm = 148;
    int dev = 0;
    cudaGetDevice(&dev);
    cudaDeviceGetAttribute(&num_sm, cudaDevAttrMultiProcessorCount, dev);
    int nblocks = 2 * num_sm;

    residual_fused_kernel<<<nblocks, THREADS, smem>>>(
        (const float4*)observes, K, poses,
        (const float4*)points, points,
        (const int4*)cidx, (const int4*)pidx,
        (float4*)d_out,
        n_obs, n_cam, n_pts);
}

// round 16
// speedup vs baseline: 1.0477x; 1.0477x over previous
#include <cuda_runtime.h>

// Bundle-adjustment reprojection residual — fused single persistent kernel.
//   d_in[0] observes  float32 [N_OBS, 2]
//   d_in[1] K         float32 [3, 3]
//   d_in[2] poses     float32 [N_CAM, 7]   (t[3], qv[3], qw)
//   d_in[3] points    float32 [N_PTS, 3]
//   d_in[4] cidx      int32   [N_OBS]
//   d_in[5] pidx      int32   [N_OBS]
// Output: float32 [N_OBS*2]  residual = proj - observe
//
// R16 (= best-measured R14 config + streaming cache hints):
//  - fused: pose->smem staging + point repack + ticket grid barrier + main loop
//  - 512 threads x 2/SM, batch-4, one LDG.128 per point gather, 2 LDS.128/pose
//  - __ldcs on idx/obs streams, __stcs on output: evict-first so L1 capacity
//    is reserved for the randomly-gathered point table lines.

#define THREADS 512
#define N_PTS_MAX 500032

__device__ float4 g_points4[N_PTS_MAX];
__device__ unsigned int g_ticket;   // monotonically increasing; never reset

__global__ __launch_bounds__(THREADS, 2) void residual_fused_kernel(
    const float4* __restrict__ obs4,
    const float* __restrict__ K,
    const float* __restrict__ poses,
    const float4* __restrict__ points4,
    const float* __restrict__ points,
    const int4* __restrict__ cidx4,
    const int4* __restrict__ pidx4,
    float4* __restrict__ out4,
    int n_obs, int n_cam, int n_pts)
{
    extern __shared__ float4 psm[];   // [n_cam] a-rows then [n_cam] b-rows
    float4* pa_t = psm;               // tx ty tz qx
    float4* pb_t = psm + n_cam;       // qy qz qw pad

    const int tid = threadIdx.x;
    const int nblocks = gridDim.x;
    const int g = blockIdx.x * THREADS + tid;
    const int gsz = nblocks * THREADS;

    // ---------------- phase 1a: stage poses into smem ----------------
    {
        float* a_f = (float*)pa_t;
        float* b_f = (float*)pb_t;
        const int n_pose_f = n_cam * 7;
        for (int idx = tid; idx < n_pose_f; idx += THREADS) {
            int c = idx / 7;
            int k = idx - c * 7;
            float v = __ldg(&poses[idx]);
            if (k < 4) a_f[c * 4 + k] = v;
            else       b_f[c * 4 + (k - 4)] = v;
        }
    }

    // ---------------- phase 1b: repack points slice ----------------
    {
        const int pq = n_pts >> 2;  // groups of 4 points (12 floats = 3 float4)
        for (int i = g; i < pq; i += gsz) {
            float4 v0 = __ldcs(&points4[3 * i]);
            float4 v1 = __ldcs(&points4[3 * i + 1]);
            float4 v2 = __ldcs(&points4[3 * i + 2]);
            g_points4[4 * i + 0] = make_float4(v0.x, v0.y, v0.z, 0.0f);
            g_points4[4 * i + 1] = make_float4(v0.w, v1.x, v1.y, 0.0f);
            g_points4[4 * i + 2] = make_float4(v1.z, v1.w, v2.x, 0.0f);
            g_points4[4 * i + 3] = make_float4(v2.y, v2.z, v2.w, 0.0f);
        }
        int r = (pq << 2) + g;
        if (r < n_pts) {
            const float* p = points + (size_t)r * 3;
            g_points4[r] = make_float4(__ldg(p), __ldg(p + 1), __ldg(p + 2), 0.0f);
        }
    }

    // ------------- ticket grid barrier (no reset across launches) -------------
    __threadfence();
    __syncthreads();
    if (tid == 0) {
        unsigned t = atomicAdd(&g_ticket, 1u);
        unsigned target = (t / (unsigned)nblocks + 1u) * (unsigned)nblocks;
        unsigned v;
        do {
            asm volatile("ld.global.acquire.gpu.u32 %0, [%1];"
                         : "=r"(v) : "l"(&g_ticket));
            if (v >= target) break;
            __nanosleep(64);
        } while (true);
    }
    __syncthreads();

    // ---------------- phase 2: main loop, 4 obs per thread ----------------
    const float fx = __ldg(&K[0]);
    const float cxx = __ldg(&K[2]);
    const float fy = __ldg(&K[4]);
    const float cyy = __ldg(&K[5]);

    const int n_quads = n_obs >> 2;

    for (int q = g; q < n_quads; q += gsz) {
        // streams: evict-first (do not pollute L1; reserve it for point lines)
        int4 c4 = __ldcs(&cidx4[q]);
        int4 p4 = __ldcs(&pidx4[q]);

        float4 ob0 = __ldcs(&obs4[2 * q]);
        float4 ob1 = __ldcs(&obs4[2 * q + 1]);

        int pis[4] = {p4.x, p4.y, p4.z, p4.w};
        int cis[4] = {c4.x, c4.y, c4.z, c4.w};

        // one LDG.128 per point (default policy: cache in L1), all 4 up front
        float4 pt[4];
        #pragma unroll
        for (int j = 0; j < 4; j++)
            pt[j] = __ldg(&g_points4[pis[j]]);

        // batch all pose LDS.128 issues before compute
        float4 pa[4], pb[4];
        #pragma unroll
        for (int j = 0; j < 4; j++) {
            pa[j] = pa_t[cis[j]];
            pb[j] = pb_t[cis[j]];
        }

        float res[8];
        float obx[4] = {ob0.x, ob0.z, ob1.x, ob1.z};
        float oby[4] = {ob0.y, ob0.w, ob1.y, ob1.w};

        #pragma unroll
        for (int j = 0; j < 4; j++) {
            float tx = pa[j].x, ty = pa[j].y, tz = pa[j].z;
            float qx = pa[j].w, qy = pb[j].x, qz = pb[j].y, qw = pb[j].z;
            float X = pt[j].x, Y = pt[j].y, Z = pt[j].z;

            float uvx = qy * Z - qz * Y;
            float uvy = qz * X - qx * Z;
            float uvz = qx * Y - qy * X;
            float wx = fmaf(qw, X, uvx);
            float wy = fmaf(qw, Y, uvy);
            float wz = fmaf(qw, Z, uvz);
            float c2x = qy * wz - qz * wy;
            float c2y = qz * wx - qx * wz;
            float c2z = qx * wy - qy * wx;
            float Xc = fmaf(2.0f, c2x, X) + tx;
            float Yc = fmaf(2.0f, c2y, Y) + ty;
            float Zc = fmaf(2.0f, c2z, Z) + tz;

            float invz = __fdividef(1.0f, Zc);
            res[2 * j + 0] = fmaf(fx * Xc, invz, cxx) - obx[j];
            res[2 * j + 1] = fmaf(fy * Yc, invz, cyy) - oby[j];
        }

        // output: streaming store (evict-first)
        __stcs(&out4[2 * q],     make_float4(res[0], res[1], res[2], res[3]));
        __stcs(&out4[2 * q + 1], make_float4(res[4], res[5], res[6], res[7]));
    }

    // ---- tail: n_obs % 4 leftovers (block 0; empty for N_OBS=5M) ----
    const int rem_base = n_quads << 2;
    if (blockIdx.x == 0) {
        const int* cidx = (const int*)cidx4;
        const int* pidx = (const int*)pidx4;
        const float2* obs2 = (const float2*)obs4;
        float2* out2 = (float2*)out4;
        for (int i = rem_base + tid; i < n_obs; i += THREADS) {
            int ci = __ldg(&cidx[i]);
            int pi = __ldg(&pidx[i]);
            float4 a = pa_t[ci];
            float4 b = pb_t[ci];
            float tx = a.x, ty = a.y, tz = a.z;
            float qx = a.w, qy = b.x, qz = b.y, qw = b.z;
            float4 p = __ldg(&g_points4[pi]);
            float X = p.x, Y = p.y, Z = p.z;

            float uvx = qy * Z - qz * Y;
            float uvy = qz * X - qx * Z;
            float uvz = qx * Y - qy * X;
            float wx = fmaf(qw, X, uvx);
            float wy = fmaf(qw, Y, uvy);
            float wz = fmaf(qw, Z, uvz);
            float c2x = qy * wz - qz * wy;
            float c2y = qz * wx - qx * wz;
            float c2z = qx * wy - qy * wx;
            float Xc = fmaf(2.0f, c2x, X) + tx;
            float Yc = fmaf(2.0f, c2y, Y) + ty;
            float Zc = fmaf(2.0f, c2z, Z) + tz;
            float invz = __fdividef(1.0f, Zc);
            float2 ob = __ldg(&obs2[i]);
            float2 r;
            r.x = fmaf(fx * Xc, invz, cxx) - ob.x;
            r.y = fmaf(fy * Yc, invz, cyy) - ob.y;
            out2[i] = r;
        }
    }
}

extern "C" void kernel_launch(void* const* d_in, const int* in_sizes, int n_in,
                              void* d_out, int out_size) {
    const float* observes = (const float*)d_in[0];
    const float* K        = (const float*)d_in[1];
    const float* poses    = (const float*)d_in[2];
    const float* points   = (const float*)d_in[3];
    const int* cidx       = (const int*)d_in[4];
    const int* pidx       = (const int*)d_in[5];

    int n_obs = in_sizes[0] / 2;
    int n_cam = in_sizes[2] / 7;
    int n_pts = in_sizes[3] / 3;
    if (n_pts > N_PTS_MAX) n_pts = N_PTS_MAX;

    int smem = n_cam * 2 * sizeof(float4);  // 64000 B for n_cam=2000

    cudaFuncSetAttribute(residual_fused_kernel,
                         cudaFuncAttributeMaxDynamicSharedMemorySize, smem);

    int num_sm = 148;
    int dev = 0;
    cudaGetDevice(&dev);
    cudaDeviceGetAttribute(&num_sm, cudaDevAttrMultiProcessorCount, dev);
    int nblocks = 2 * num_sm;

    residual_fused_kernel<<<nblocks, THREADS, smem>>>(
        (const float4*)observes, K, poses,
        (const float4*)points, points,
        (const int4*)cidx, (const int4*)pidx,
        (float4*)d_out,
        n_obs, n_cam, n_pts);
}